// round 2
// baseline (speedup 1.0000x reference)
#include <cuda_runtime.h>
#include <math.h>

// Problem constants (fixed shapes from reference)
#define N_ROWS 131072   // 32*64*64
#define DIM    64
#define KCB    512

// Output layout (concatenated reference outputs, float32):
// quantized [N_ROWS*DIM], perplexity [1], encodings [N_ROWS*KCB],
// encoding_indices [N_ROWS], distances [N_ROWS*KCB]
// NOTE: the scalar perplexity misaligns everything after it to 4-byte
// alignment only -> NO vector (8/16B) loads/stores into outE/outD.
#define OFF_Q 0
#define OFF_P (N_ROWS * DIM)
#define OFF_E (OFF_P + 1)
#define OFF_I (OFF_E + (size_t)N_ROWS * KCB)
#define OFF_D (OFF_I + N_ROWS)

// Scratch (no allocations allowed)
__device__ unsigned long long g_argkey[N_ROWS];
__device__ float g_rownorm[N_ROWS];
__device__ float g_colnorm[KCB];
__device__ unsigned int g_count[KCB];

// ---------------------------------------------------------------------------
// helpers
// ---------------------------------------------------------------------------
__device__ __forceinline__ unsigned int forder(float f) {
    unsigned int u = __float_as_uint(f);
    unsigned int mask = ((int)u >> 31) | 0x80000000u;
    return u ^ mask;  // monotonic map float -> uint
}

__device__ __forceinline__ unsigned long long pk2(float lo, float hi) {
    unsigned long long r;
    asm("mov.b64 %0, {%1,%2};" : "=l"(r) : "f"(lo), "f"(hi));
    return r;
}
__device__ __forceinline__ void upk2(unsigned long long v, float& lo, float& hi) {
    asm("mov.b64 {%0,%1}, %2;" : "=f"(lo), "=f"(hi) : "l"(v));
}
__device__ __forceinline__ void fma2(unsigned long long& acc, unsigned long long a,
                                     unsigned long long b) {
    asm("fma.rn.f32x2 %0, %1, %2, %0;" : "+l"(acc) : "l"(a), "l"(b));
}

// ---------------------------------------------------------------------------
// 1) init scratch
// ---------------------------------------------------------------------------
__global__ void init_k() {
    int i = blockIdx.x * blockDim.x + threadIdx.x;
    if (i < N_ROWS) g_argkey[i] = 0xFFFFFFFFFFFFFFFFULL;
    if (i < KCB) g_count[i] = 0u;
}

// ---------------------------------------------------------------------------
// 2) row norms ||x||^2
// ---------------------------------------------------------------------------
__global__ void rownorm_k(const float* __restrict__ X) {
    int r = blockIdx.x * blockDim.x + threadIdx.x;
    if (r >= N_ROWS) return;
    const float4* p = (const float4*)(X + (size_t)r * DIM);
    float s = 0.f;
#pragma unroll
    for (int i = 0; i < DIM / 4; i++) {
        float4 v = p[i];
        s += v.x * v.x + v.y * v.y + v.z * v.z + v.w * v.w;
    }
    g_rownorm[r] = s;
}

// ---------------------------------------------------------------------------
// 3) codebook norms ||e||^2
// ---------------------------------------------------------------------------
__global__ void colnorm_k(const float* __restrict__ CB) {
    int r = blockIdx.x * blockDim.x + threadIdx.x;
    if (r >= KCB) return;
    const float4* p = (const float4*)(CB + (size_t)r * DIM);
    float s = 0.f;
#pragma unroll
    for (int i = 0; i < DIM / 4; i++) {
        float4 v = p[i];
        s += v.x * v.x + v.y * v.y + v.z * v.z + v.w * v.w;
    }
    g_colnorm[r] = s;
}

// ---------------------------------------------------------------------------
// 4) GEMM + distances + per-row argmin
// Tile: 128 rows x 128 cols, full K(=64). 256 threads, 8x8 microtile.
// Thread (tx,ty) owns rows ty*8..+7 and columns {tx + 16*c : c=0..7}
// (lane-interleaved columns -> coalesced SCALAR distance stores, since outD
// is only 4B-aligned).
// Accumulators packed f32x2 row-pairs (fma.rn.f32x2 = 2 FMA/instr).
// ---------------------------------------------------------------------------
#define SM_STRIDE 132
#define GEMM_SMEM_BYTES ((2 * 64 * SM_STRIDE) * 4 + 128 * 8)

__global__ __launch_bounds__(256, 2) void gemm_k(const float* __restrict__ A,
                                                 const float* __restrict__ B,
                                                 float* __restrict__ outD) {
    extern __shared__ float sm[];
    float* As = sm;                        // [64][132]
    float* Bs = sm + 64 * SM_STRIDE;       // [64][132]
    unsigned long long* red = (unsigned long long*)(sm + 2 * 64 * SM_STRIDE);  // [128]

    const int tid = threadIdx.x;
    const int tx = tid & 15;   // col lane
    const int ty = tid >> 4;   // row group
    const int bm0 = blockIdx.y * 128;
    const int bk0 = blockIdx.x * 128;

    // Load A/B tiles (128 rows x 64) transposed into smem [d][m]
    {
        const float4* Ag = (const float4*)(A + (size_t)bm0 * DIM);
        const float4* Bg = (const float4*)(B + (size_t)bk0 * DIM);
#pragma unroll
        for (int i = 0; i < 8; i++) {
            int t4 = tid + i * 256;          // 0..2047
            int m = t4 >> 4;                 // 16 float4 per row
            int d = (t4 & 15) * 4;
            float4 va = Ag[t4];
            As[(d + 0) * SM_STRIDE + m] = va.x;
            As[(d + 1) * SM_STRIDE + m] = va.y;
            As[(d + 2) * SM_STRIDE + m] = va.z;
            As[(d + 3) * SM_STRIDE + m] = va.w;
            float4 vb = Bg[t4];
            Bs[(d + 0) * SM_STRIDE + m] = vb.x;
            Bs[(d + 1) * SM_STRIDE + m] = vb.y;
            Bs[(d + 2) * SM_STRIDE + m] = vb.z;
            Bs[(d + 3) * SM_STRIDE + m] = vb.w;
        }
    }
    if (tid < 128) red[tid] = 0xFFFFFFFFFFFFFFFFULL;
    __syncthreads();

    // acc[p][c]: packed pair = (row 2p, row 2p+1) for column slot c
    unsigned long long acc[4][8];
#pragma unroll
    for (int p = 0; p < 4; p++)
#pragma unroll
        for (int c = 0; c < 8; c++) acc[p][c] = 0ULL;

#pragma unroll 8
    for (int d = 0; d < 64; d++) {
        float4 a0 = *(const float4*)&As[d * SM_STRIDE + ty * 8];
        float4 a1 = *(const float4*)&As[d * SM_STRIDE + ty * 8 + 4];
        unsigned long long ap[4];
        ap[0] = pk2(a0.x, a0.y);
        ap[1] = pk2(a0.z, a0.w);
        ap[2] = pk2(a1.x, a1.y);
        ap[3] = pk2(a1.z, a1.w);
        unsigned long long bb[8];
#pragma unroll
        for (int c = 0; c < 8; c++) {
            float bv = Bs[d * SM_STRIDE + tx + 16 * c];
            bb[c] = pk2(bv, bv);
        }
#pragma unroll
        for (int p = 0; p < 4; p++)
#pragma unroll
            for (int c = 0; c < 8; c++) fma2(acc[p][c], ap[p], bb[c]);
    }

    // Epilogue: distances + local argmin
    float rn[8], cn[8];
#pragma unroll
    for (int r = 0; r < 8; r++) rn[r] = g_rownorm[bm0 + ty * 8 + r];
#pragma unroll
    for (int c = 0; c < 8; c++) cn[c] = g_colnorm[bk0 + tx + 16 * c];

    float dot[8][8];
#pragma unroll
    for (int p = 0; p < 4; p++)
#pragma unroll
        for (int c = 0; c < 8; c++) {
            float lo, hi;
            upk2(acc[p][c], lo, hi);
            dot[2 * p][c] = lo;
            dot[2 * p + 1][c] = hi;
        }

#pragma unroll
    for (int r = 0; r < 8; r++) {
        int gm = bm0 + ty * 8 + r;
        float* dst = outD + (size_t)gm * KCB + bk0 + tx;
        float v[8];
#pragma unroll
        for (int c = 0; c < 8; c++) v[c] = (rn[r] - 2.f * dot[r][c]) + cn[c];
        // coalesced scalar stores: lanes 0..15 consecutive per c
#pragma unroll
        for (int c = 0; c < 8; c++) dst[16 * c] = v[c];
        float mn = v[0];
        int mc = 0;
#pragma unroll
        for (int c = 1; c < 8; c++)
            if (v[c] < mn) { mn = v[c]; mc = c; }
        unsigned long long key =
            ((unsigned long long)forder(mn) << 32) | (unsigned)(bk0 + tx + 16 * mc);
        atomicMin(&red[ty * 8 + r], key);
    }
    __syncthreads();
    if (tid < 128) atomicMin(&g_argkey[bm0 + tid], red[tid]);
}

// ---------------------------------------------------------------------------
// 5) finalize: quantized, encodings (one-hot), indices, histogram. Warp/row.
// ---------------------------------------------------------------------------
__global__ void finalize_k(const float* __restrict__ X, const float* __restrict__ CB,
                           float* __restrict__ outQ, float* __restrict__ outE,
                           float* __restrict__ outI) {
    int warp = blockIdx.x * (blockDim.x >> 5) + (threadIdx.x >> 5);
    int lane = threadIdx.x & 31;
    if (warp >= N_ROWS) return;

    unsigned long long key = g_argkey[warp];
    int idx = (int)(key & 0xFFFFFFFFu);

    // quantized: x + (cb - x), 2 floats per lane (outQ is 16B-aligned)
    const float2* xp = (const float2*)(X + (size_t)warp * DIM);
    const float2* cp = (const float2*)(CB + (size_t)idx * DIM);
    float2 x = xp[lane];
    float2 c = cp[lane];
    float2 q;
    q.x = x.x + (c.x - x.x);
    q.y = x.y + (c.y - x.y);
    ((float2*)(outQ + (size_t)warp * DIM))[lane] = q;

    if (lane == 0) {
        outI[warp] = (float)idx;
        atomicAdd(&g_count[idx], 1u);
    }

    // one-hot encodings: SCALAR coalesced stores (outE only 4B-aligned)
    float* ep = outE + (size_t)warp * KCB;
#pragma unroll
    for (int j = 0; j < 16; j++) {
        int col = j * 32 + lane;
        ep[col] = (col == idx) ? 1.f : 0.f;
    }
}

// ---------------------------------------------------------------------------
// 6) perplexity
// ---------------------------------------------------------------------------
__global__ void perp_k(float* __restrict__ outP) {
    __shared__ float s[KCB];
    int t = threadIdx.x;
    float p = (float)g_count[t] / (float)N_ROWS;
    s[t] = p * logf(p + 1e-10f);
    __syncthreads();
    for (int o = KCB / 2; o > 0; o >>= 1) {
        if (t < o) s[t] += s[t + o];
        __syncthreads();
    }
    if (t == 0) outP[0] = expf(-s[0]);
}

// ---------------------------------------------------------------------------
extern "C" void kernel_launch(void* const* d_in, const int* in_sizes, int n_in,
                              void* d_out, int out_size) {
    const float* X = (const float*)d_in[0];
    const float* CB = (const float*)d_in[1];
    // robustness: identify by size (inputs: 8388608, codebook: 32768)
    if (n_in >= 2 && in_sizes[0] == KCB * DIM) {
        X = (const float*)d_in[1];
        CB = (const float*)d_in[0];
    }
    float* out = (float*)d_out;
    float* outQ = out + OFF_Q;
    float* outP = out + OFF_P;
    float* outE = out + OFF_E;
    float* outI = out + OFF_I;
    float* outD = out + OFF_D;

    cudaFuncSetAttribute(gemm_k, cudaFuncAttributeMaxDynamicSharedMemorySize,
                         GEMM_SMEM_BYTES);

    init_k<<<N_ROWS / 256, 256>>>();
    rownorm_k<<<N_ROWS / 256, 256>>>(X);
    colnorm_k<<<2, 256>>>(CB);
    gemm_k<<<dim3(KCB / 128, N_ROWS / 128), 256, GEMM_SMEM_BYTES>>>(X, CB, outD);
    finalize_k<<<N_ROWS / 8, 256>>>(X, CB, outQ, outE, outI);
    perp_k<<<1, KCB>>>(outP);
}